// round 2
// baseline (speedup 1.0000x reference)
#include <cuda_runtime.h>
#include <cuda_bf16.h>
#include <cstdint>

// ---------------- problem constants ----------------
#define T_STEPS 4096
#define VOCAB   32000
#define EMBD    192
#define HIDDEN  512

// ---------------- device scratch (no allocs allowed) ----------------
__device__ float  g_xe  [T_STEPS * EMBD];        // gathered embeddings   3 MB
__device__ float  g_xseq[T_STEPS * HIDDEN];      // x projections         8 MB
__device__ float  g_gx  [T_STEPS * 4 * HIDDEN];  // x-part of gate preact 32 MB
__device__ float  g_hs  [T_STEPS * HIDDEN];      // hidden states         8 MB
__device__ float  g_wxp [HIDDEN * 4 * HIDDEN];   // repacked x-part gate weights [512][2048]
__device__ float  g_bx  [4 * HIDDEN];            // gate biases concat
__device__ float4 g_wh4 [32 * 512 * 16];         // recurrent weights, per-thread layout 4 MB
__device__ float  g_hbuf[2][HIDDEN];             // h ping-pong
__device__ unsigned g_bar;                       // global step barrier

// ---------------- init + weight repack ----------------
__global__ void init_repack(const float* __restrict__ Wf, const float* __restrict__ Wis,
                            const float* __restrict__ Wit, const float* __restrict__ Wo,
                            const float* __restrict__ bf, const float* __restrict__ bis,
                            const float* __restrict__ bit, const float* __restrict__ bo)
{
    const int stride = gridDim.x * blockDim.x;
    const int tid0 = blockIdx.x * blockDim.x + threadIdx.x;
    const float* Ws[4] = {Wf, Wis, Wit, Wo};
    const float* bs[4] = {bf, bis, bit, bo};

    // x-part weights: Wxp[k][g*512+j] = W_g[(512+k)*512 + j]   (rows 512..1023 are the x part)
    for (int idx = tid0; idx < 512 * 2048; idx += stride) {
        int k = idx >> 11;
        int c = idx & 2047;
        int g = c >> 9;
        int j = c & 511;
        g_wxp[idx] = Ws[g][(512 + k) * 512 + j];
    }
    for (int idx = tid0; idx < 2048; idx += stride)
        g_bx[idx] = bs[idx >> 9][idx & 511];

    // recurrent weights (rows 0..511 = h part), per-thread register layout:
    // CTA r (32 CTAs), thread t (512), output q (4), chunk i (4)
    // lane l = t&31, warp w = t>>5 ; k = 4*l + 128*i ; o_local = w*4+q ; g=o>>4 ; jj=o&15 ; j=r*16+jj
    for (int idx = tid0; idx < 262144; idx += stride) {
        int i = idx & 3;
        int q = (idx >> 2) & 3;
        int t = (idx >> 4) & 511;
        int r = idx >> 13;
        int l = t & 31, w = t >> 5;
        int k = 4 * l + 128 * i;
        int o = w * 4 + q;
        int g = o >> 4;
        int jj = o & 15;
        int j = r * 16 + jj;
        const float* W = Ws[g];
        g_wh4[idx] = make_float4(W[(k + 0) * 512 + j], W[(k + 1) * 512 + j],
                                 W[(k + 2) * 512 + j], W[(k + 3) * 512 + j]);
    }
    for (int idx = tid0; idx < 1024; idx += stride)
        (&g_hbuf[0][0])[idx] = 0.f;
    if (tid0 == 0) g_bar = 0u;
}

// ---------------- embedding gather ----------------
__global__ void gather_emb(const int* __restrict__ X, const float* __restrict__ emb)
{
    int idx = blockIdx.x * blockDim.x + threadIdx.x;
    if (idx >= T_STEPS * EMBD) return;
    int t = idx / EMBD;
    int k = idx % EMBD;
    g_xe[idx] = emb[(size_t)X[t] * EMBD + k];
}

// ---------------- generic SGEMM + bias  C[M,N] = A[M,K]@B[K,N] + bias ----------------
// 128x128 tile, BK=8, 256 threads, 8x8 per thread. M%128==0, N%128==0, K%8==0.
__global__ __launch_bounds__(256) void sgemm_bias(const float* __restrict__ A,
                                                  const float* __restrict__ B,
                                                  const float* __restrict__ bias,
                                                  float* __restrict__ C,
                                                  int M, int N, int K)
{
    __shared__ float As[8][128];
    __shared__ float Bs[8][128];
    const int tid = threadIdx.x;
    const int m0 = blockIdx.x * 128;
    const int n0 = blockIdx.y * 128;
    const int arow = tid >> 1, acol = (tid & 1) * 4;
    const int brow = tid >> 5, bcol = (tid & 31) * 4;
    const int tm = (tid >> 4) * 8, tn = (tid & 15) * 8;

    float acc[8][8];
#pragma unroll
    for (int i = 0; i < 8; i++)
#pragma unroll
        for (int j = 0; j < 8; j++) acc[i][j] = 0.f;

    for (int k0 = 0; k0 < K; k0 += 8) {
        float4 av = *(const float4*)(A + (size_t)(m0 + arow) * K + k0 + acol);
        float4 bv = *(const float4*)(B + (size_t)(k0 + brow) * N + n0 + bcol);
        As[acol + 0][arow] = av.x;
        As[acol + 1][arow] = av.y;
        As[acol + 2][arow] = av.z;
        As[acol + 3][arow] = av.w;
        *(float4*)&Bs[brow][bcol] = bv;
        __syncthreads();
#pragma unroll
        for (int kk = 0; kk < 8; kk++) {
            float ra[8], rb[8];
            *(float4*)(ra)     = *(const float4*)&As[kk][tm];
            *(float4*)(ra + 4) = *(const float4*)&As[kk][tm + 4];
            *(float4*)(rb)     = *(const float4*)&Bs[kk][tn];
            *(float4*)(rb + 4) = *(const float4*)&Bs[kk][tn + 4];
#pragma unroll
            for (int i = 0; i < 8; i++)
#pragma unroll
                for (int j = 0; j < 8; j++)
                    acc[i][j] = fmaf(ra[i], rb[j], acc[i][j]);
        }
        __syncthreads();
    }

    float bvreg[8];
#pragma unroll
    for (int j = 0; j < 8; j++) bvreg[j] = bias[n0 + tn + j];
#pragma unroll
    for (int i = 0; i < 8; i++) {
        size_t row = (size_t)(m0 + tm + i) * N + n0 + tn;
        float4 o0 = make_float4(acc[i][0] + bvreg[0], acc[i][1] + bvreg[1],
                                acc[i][2] + bvreg[2], acc[i][3] + bvreg[3]);
        float4 o1 = make_float4(acc[i][4] + bvreg[4], acc[i][5] + bvreg[5],
                                acc[i][6] + bvreg[6], acc[i][7] + bvreg[7]);
        *(float4*)(C + row)     = o0;
        *(float4*)(C + row + 4) = o1;
    }
}

// ---------------- recurrence: 32 persistent CTAs x 512 threads ----------------
__device__ __forceinline__ float fast_sigmoid(float x)
{
    return __fdividef(1.f, 1.f + __expf(-x));
}
__device__ __forceinline__ float fast_tanh(float x)
{
    return 2.f * __fdividef(1.f, 1.f + __expf(-2.f * x)) - 1.f;
}

__global__ __launch_bounds__(512, 1) void lstm_rec()
{
    __shared__ __align__(16) float h_s[512];
    __shared__ float gates_s[64];
    const int tid = threadIdx.x;
    const int r = blockIdx.x;       // 0..31
    const int w = tid >> 5, l = tid & 31;

    // per-thread recurrent weights in registers: 4 outputs x 4 chunks x float4 = 64 regs
    float4 wt[4][4];
    {
        const float4* wb = g_wh4 + ((size_t)(r * 512 + tid)) * 16;
#pragma unroll
        for (int q = 0; q < 4; q++)
#pragma unroll
            for (int i = 0; i < 4; i++) wt[q][i] = wb[q * 4 + i];
    }

    float c = 0.f;
    float gx0 = 0.f, gx1 = 0.f, gx2 = 0.f, gx3 = 0.f;
    if (tid < 16) {
        const float* gp = g_gx + (size_t)r * 16 + tid;
        gx0 = __ldg(gp);
        gx1 = __ldg(gp + 512);
        gx2 = __ldg(gp + 1024);
        gx3 = __ldg(gp + 1536);
    }
    if (tid < 256) {
        float2 v = __ldcg((const float2*)(&g_hbuf[1][2 * tid]));
        *(float2*)&h_s[2 * tid] = v;
    }
    __syncthreads();

    for (int t = 0; t < T_STEPS; t++) {
        // ---- dot: each thread, 4 outputs over its 16 h values ----
        float a0 = 0.f, a1 = 0.f, a2 = 0.f, a3 = 0.f;
#pragma unroll
        for (int i = 0; i < 4; i++) {
            float4 h4 = *(const float4*)&h_s[4 * l + 128 * i];
            a0 = fmaf(h4.x, wt[0][i].x, a0); a0 = fmaf(h4.y, wt[0][i].y, a0);
            a0 = fmaf(h4.z, wt[0][i].z, a0); a0 = fmaf(h4.w, wt[0][i].w, a0);
            a1 = fmaf(h4.x, wt[1][i].x, a1); a1 = fmaf(h4.y, wt[1][i].y, a1);
            a1 = fmaf(h4.z, wt[1][i].z, a1); a1 = fmaf(h4.w, wt[1][i].w, a1);
            a2 = fmaf(h4.x, wt[2][i].x, a2); a2 = fmaf(h4.y, wt[2][i].y, a2);
            a2 = fmaf(h4.z, wt[2][i].z, a2); a2 = fmaf(h4.w, wt[2][i].w, a2);
            a3 = fmaf(h4.x, wt[3][i].x, a3); a3 = fmaf(h4.y, wt[3][i].y, a3);
            a3 = fmaf(h4.z, wt[3][i].z, a3); a3 = fmaf(h4.w, wt[3][i].w, a3);
        }
#pragma unroll
        for (int off = 16; off; off >>= 1) {
            a0 += __shfl_xor_sync(0xffffffffu, a0, off);
            a1 += __shfl_xor_sync(0xffffffffu, a1, off);
            a2 += __shfl_xor_sync(0xffffffffu, a2, off);
            a3 += __shfl_xor_sync(0xffffffffu, a3, off);
        }
        if (l == 0) {
            gates_s[w * 4 + 0] = a0;
            gates_s[w * 4 + 1] = a1;
            gates_s[w * 4 + 2] = a2;
            gates_s[w * 4 + 3] = a3;
        }
        __syncthreads();

        // ---- finalize: 16 threads own c[jj], h[jj] ----
        if (tid < 16) {
            float pf = gates_s[tid]      + gx0;
            float pi = gates_s[16 + tid] + gx1;
            float pt = gates_s[32 + tid] + gx2;
            float po = gates_s[48 + tid] + gx3;
            float f   = fast_sigmoid(pf);
            float ig  = fast_sigmoid(pi);
            float itv = fast_tanh(pt);
            float og  = fast_sigmoid(po);
            c = c * f + ig * itv;
            float h = fast_tanh(c) * og;
            g_hbuf[t & 1][r * 16 + tid] = h;
            g_hs[(size_t)t * 512 + r * 16 + tid] = h;
            if (t + 1 < T_STEPS) {
                const float* gp = g_gx + (size_t)(t + 1) * 2048 + r * 16 + tid;
                gx0 = __ldg(gp);
                gx1 = __ldg(gp + 512);
                gx2 = __ldg(gp + 1024);
                gx3 = __ldg(gp + 1536);
            }
            __threadfence();
        }
        __syncthreads();

        // ---- global step barrier ----
        if (tid == 0) {
            atomicAdd(&g_bar, 1u);
            unsigned target = 32u * (unsigned)(t + 1);
            unsigned v;
            do {
                asm volatile("ld.acquire.gpu.global.u32 %0, [%1];"
                             : "=r"(v) : "l"(&g_bar) : "memory");
            } while (v < target);
        }
        __syncthreads();

        // ---- pull full h(t) for next step ----
        if (tid < 256) {
            float2 v = __ldcg((const float2*)(&g_hbuf[t & 1][2 * tid]));
            *(float2*)&h_s[2 * tid] = v;
        }
        __syncthreads();
    }
}

// ---------------- launch ----------------
template <typename Tsym>
static void* symaddr(Tsym& s)
{
    void* p = nullptr;
    cudaGetSymbolAddress(&p, s);
    return p;
}

extern "C" void kernel_launch(void* const* d_in, const int* in_sizes, int n_in,
                              void* d_out, int out_size)
{
    const int*   X      = (const int*)  d_in[0];
    const float* emb    = (const float*)d_in[1];
    const float* W_in   = (const float*)d_in[2];
    const float* b_in   = (const float*)d_in[3];
    const float* W_f    = (const float*)d_in[4];
    const float* b_f    = (const float*)d_in[5];
    const float* W_is   = (const float*)d_in[6];
    const float* b_is   = (const float*)d_in[7];
    const float* W_it   = (const float*)d_in[8];
    const float* b_it   = (const float*)d_in[9];
    const float* W_o    = (const float*)d_in[10];
    const float* b_o    = (const float*)d_in[11];
    const float* W_head = (const float*)d_in[12];
    const float* b_head = (const float*)d_in[13];
    float* out = (float*)d_out;

    float* xe   = (float*)symaddr(g_xe);
    float* xseq = (float*)symaddr(g_xseq);
    float* gx   = (float*)symaddr(g_gx);
    float* hs   = (float*)symaddr(g_hs);
    float* wxp  = (float*)symaddr(g_wxp);
    float* bx   = (float*)symaddr(g_bx);

    // 1. init scratch + repack weights (also zeroes barrier + h ping-pong)
    init_repack<<<512, 256>>>(W_f, W_is, W_it, W_o, b_f, b_is, b_it, b_o);

    // 2. embedding gather
    gather_emb<<<(T_STEPS * EMBD + 255) / 256, 256>>>(X, emb);

    // 3. x projection: xseq = xe @ W_in + b_in   [4096,192]x[192,512]
    sgemm_bias<<<dim3(T_STEPS / 128, HIDDEN / 128), 256>>>(xe, W_in, b_in, xseq,
                                                           T_STEPS, HIDDEN, EMBD);

    // 4. gate x-part: gx = xseq @ Wxp + bx   [4096,512]x[512,2048]
    sgemm_bias<<<dim3(T_STEPS / 128, (4 * HIDDEN) / 128), 256>>>(xseq, wxp, bx, gx,
                                                                 T_STEPS, 4 * HIDDEN, HIDDEN);

    // 5. recurrence (persistent, 32 CTAs)
    lstm_rec<<<32, 512>>>();

    // 6. head: out = hs @ W_head + b_head   [4096,512]x[512,32000]
    sgemm_bias<<<dim3(T_STEPS / 128, VOCAB / 128), 256>>>(hs, W_head, b_head, out,
                                                          T_STEPS, VOCAB, HIDDEN);
}

// round 3
// speedup vs baseline: 1.0298x; 1.0298x over previous
#include <cuda_runtime.h>
#include <cuda_bf16.h>
#include <cstdint>

// ---------------- problem constants ----------------
#define T_STEPS 4096
#define VOCAB   32000
#define EMBD    192
#define HIDDEN  512

typedef unsigned long long u64;

// ---------------- device scratch (no allocs allowed) ----------------
__device__ float g_xe  [T_STEPS * EMBD];        // gathered embeddings
__device__ float g_xseq[T_STEPS * HIDDEN];      // x projections
__device__ float g_gx  [T_STEPS * 4 * HIDDEN];  // x-part of gate preact (+bias)
__device__ float g_hs  [T_STEPS * HIDDEN];      // hidden states
__device__ float g_wxp [HIDDEN * 4 * HIDDEN];   // repacked x-part gate weights [512][2048]
__device__ float g_bx  [4 * HIDDEN];            // gate biases concat
__device__ u64   g_wh2 [32 * 16 * 32 * 32];     // recurrent weights, f32x2 per-thread layout (4MB)
__device__ u64   g_htag[HIDDEN];                // (h value, step tag) atoms

// ---------------- f32x2 helpers ----------------
__device__ __forceinline__ u64 pack2(float x, float y)
{
    u64 r;
    asm("mov.b64 %0, {%1, %2};" : "=l"(r) : "f"(x), "f"(y));
    return r;
}
__device__ __forceinline__ void unpack2(u64 v, float& x, float& y)
{
    asm("mov.b64 {%0, %1}, %2;" : "=f"(x), "=f"(y) : "l"(v));
}
__device__ __forceinline__ u64 fma2(u64 a, u64 b, u64 c)
{
    u64 d;
    asm("fma.rn.f32x2 %0, %1, %2, %3;" : "=l"(d) : "l"(a), "l"(b), "l"(c));
    return d;
}

// ---------------- init + weight repack ----------------
__global__ void init_repack(const float* __restrict__ Wf, const float* __restrict__ Wis,
                            const float* __restrict__ Wit, const float* __restrict__ Wo,
                            const float* __restrict__ bf, const float* __restrict__ bis,
                            const float* __restrict__ bit, const float* __restrict__ bo)
{
    const int stride = gridDim.x * blockDim.x;
    const int tid0 = blockIdx.x * blockDim.x + threadIdx.x;
    const float* Ws[4] = {Wf, Wis, Wit, Wo};
    const float* bs[4] = {bf, bis, bit, bo};

    // x-part weights: Wxp[k][g*512+j] = W_g[(512+k)*512 + j]
    for (int idx = tid0; idx < 512 * 2048; idx += stride) {
        int k = idx >> 11;
        int c = idx & 2047;
        int g = c >> 9;
        int j = c & 511;
        g_wxp[idx] = Ws[g][(512 + k) * 512 + j];
    }
    for (int idx = tid0; idx < 2048; idx += stride)
        g_bx[idx] = bs[idx >> 9][idx & 511];

    // recurrent h-part weights -> per-thread f32x2 layout.
    // idx bits: h2(1) m(4) l(5) w(4) r(5)
    // thread (r,w,l): p=l&7, q=l>>3, output j=r*16+w, gate q.
    // k = p*4 + 32*m + 2*h2 ; value = (W_q[k][j], W_q[k+1][j])
    for (int idx = tid0; idx < 32 * 16 * 32 * 32; idx += stride) {
        int h2 = idx & 1;
        int m  = (idx >> 1) & 15;
        int l  = (idx >> 5) & 31;
        int w  = (idx >> 10) & 15;
        int r  = idx >> 14;
        int p = l & 7, q = l >> 3;
        int j = r * 16 + w;
        int k = p * 4 + 32 * m + 2 * h2;
        const float* W = Ws[q];
        unsigned lo = __float_as_uint(W[(size_t)k * 512 + j]);
        unsigned hi = __float_as_uint(W[(size_t)(k + 1) * 512 + j]);
        g_wh2[idx] = (u64)lo | ((u64)hi << 32);
    }
    // h tags: value 0.0f, tag 0
    for (int idx = tid0; idx < HIDDEN; idx += stride)
        g_htag[idx] = 0ull;
}

// ---------------- embedding gather ----------------
__global__ void gather_emb(const int* __restrict__ X, const float* __restrict__ emb)
{
    int idx = blockIdx.x * blockDim.x + threadIdx.x;
    if (idx >= T_STEPS * EMBD) return;
    int t = idx / EMBD;
    int k = idx % EMBD;
    g_xe[idx] = emb[(size_t)X[t] * EMBD + k];
}

// ---------------- SGEMM + bias  C[M,N] = A[M,K]@B[K,N] + bias ----------------
// 128x128 tile, BK=8, 256 threads, 8x8 per thread, f32x2 FMAs.
__global__ __launch_bounds__(256) void sgemm_bias(const float* __restrict__ A,
                                                  const float* __restrict__ B,
                                                  const float* __restrict__ bias,
                                                  float* __restrict__ C,
                                                  int M, int N, int K)
{
    __shared__ __align__(16) float As[8][128];
    __shared__ __align__(16) float Bs[8][128];
    const int tid = threadIdx.x;
    const int m0 = blockIdx.x * 128;
    const int n0 = blockIdx.y * 128;
    const int arow = tid >> 1, acol = (tid & 1) * 4;
    const int brow = tid >> 5, bcol = (tid & 31) * 4;
    const int tm = (tid >> 4) * 8, tn = (tid & 15) * 8;

    u64 acc2[8][4];
#pragma unroll
    for (int i = 0; i < 8; i++)
#pragma unroll
        for (int j = 0; j < 4; j++) acc2[i][j] = 0ull;

    for (int k0 = 0; k0 < K; k0 += 8) {
        float4 av = *(const float4*)(A + (size_t)(m0 + arow) * K + k0 + acol);
        float4 bv = *(const float4*)(B + (size_t)(k0 + brow) * N + n0 + bcol);
        As[acol + 0][arow] = av.x;
        As[acol + 1][arow] = av.y;
        As[acol + 2][arow] = av.z;
        As[acol + 3][arow] = av.w;
        *(float4*)&Bs[brow][bcol] = bv;
        __syncthreads();
#pragma unroll
        for (int kk = 0; kk < 8; kk++) {
            float ra[8];
            *(float4*)(ra)     = *(const float4*)&As[kk][tm];
            *(float4*)(ra + 4) = *(const float4*)&As[kk][tm + 4];
            ulonglong2 rbA = *(const ulonglong2*)&Bs[kk][tn];
            ulonglong2 rbB = *(const ulonglong2*)&Bs[kk][tn + 4];
            u64 rb2[4] = {rbA.x, rbA.y, rbB.x, rbB.y};
#pragma unroll
            for (int i = 0; i < 8; i++) {
                u64 ad = pack2(ra[i], ra[i]);
#pragma unroll
                for (int jj = 0; jj < 4; jj++)
                    acc2[i][jj] = fma2(ad, rb2[jj], acc2[i][jj]);
            }
        }
        __syncthreads();
    }

    float bvreg[8];
#pragma unroll
    for (int j = 0; j < 8; j++) bvreg[j] = bias[n0 + tn + j];
#pragma unroll
    for (int i = 0; i < 8; i++) {
        float cvals[8];
#pragma unroll
        for (int jj = 0; jj < 4; jj++)
            unpack2(acc2[i][jj], cvals[2 * jj], cvals[2 * jj + 1]);
        size_t row = (size_t)(m0 + tm + i) * N + n0 + tn;
        float4 o0 = make_float4(cvals[0] + bvreg[0], cvals[1] + bvreg[1],
                                cvals[2] + bvreg[2], cvals[3] + bvreg[3]);
        float4 o1 = make_float4(cvals[4] + bvreg[4], cvals[5] + bvreg[5],
                                cvals[6] + bvreg[6], cvals[7] + bvreg[7]);
        *(float4*)(C + row)     = o0;
        *(float4*)(C + row + 4) = o1;
    }
}

// ---------------- recurrence: 32 persistent CTAs x 512 threads ----------------
__device__ __forceinline__ float fast_sigmoid(float x)
{
    return __fdividef(1.f, 1.f + __expf(-x));
}
__device__ __forceinline__ float fast_tanh(float x)
{
    return 2.f * __fdividef(1.f, 1.f + __expf(-2.f * x)) - 1.f;
}

__global__ __launch_bounds__(512, 1) void lstm_rec()
{
    __shared__ __align__(16) float h_s[2][HIDDEN];
    const int tid = threadIdx.x;
    const int r = blockIdx.x;            // 0..31
    const int w = tid >> 5, l = tid & 31;
    const int p = l & 7, q = l >> 3;
    const int j = r * 16 + w;            // this warp's hidden index

    // per-thread recurrent weights in registers: 32 f32x2 (64 regs)
    u64 wt[32];
    {
        const u64* wb = g_wh2 + ((size_t)((r * 16 + w) * 32 + l)) * 32;
#pragma unroll
        for (int m2 = 0; m2 < 32; m2++) wt[m2] = wb[m2];
    }

    u64* ht = g_htag;
    const float* gxq = g_gx + q * 512 + j;
    float c = 0.f;

    for (int t = 0; t < T_STEPS; t++) {
        // prefetch this step's x-part gate preactivation (lanes p==0 use it)
        float gxv = 0.f;
        if (p == 0) gxv = __ldcg(gxq + (size_t)t * 2048);

        // ---- poll own (h, tag) atom until tag == t, share via smem ----
        unsigned lo, hi;
        do {
            asm volatile("ld.relaxed.gpu.global.v2.u32 {%0,%1}, [%2];"
                         : "=r"(lo), "=r"(hi) : "l"(ht + tid) : "memory");
        } while (hi != (unsigned)t);
        h_s[t & 1][tid] = __uint_as_float(lo);
        __syncthreads();

        // ---- dot: this thread covers 64 h-elems for output (j, gate q) ----
        const float* hb = &h_s[t & 1][0];
        u64 acc[4] = {0ull, 0ull, 0ull, 0ull};
#pragma unroll
        for (int m = 0; m < 16; m++) {
            float4 h4 = *(const float4*)(hb + p * 4 + 32 * m);
            u64 hA = pack2(h4.x, h4.y);
            u64 hB = pack2(h4.z, h4.w);
            acc[(2 * m) & 3]     = fma2(hA, wt[2 * m],     acc[(2 * m) & 3]);
            acc[(2 * m + 1) & 3] = fma2(hB, wt[2 * m + 1], acc[(2 * m + 1) & 3]);
        }
        float x0, y0, x1, y1, x2, y2, x3, y3;
        unpack2(acc[0], x0, y0);
        unpack2(acc[1], x1, y1);
        unpack2(acc[2], x2, y2);
        unpack2(acc[3], x3, y3);
        float partial = ((x0 + y0) + (x1 + y1)) + ((x2 + y2) + (x3 + y3)) + gxv;

        // ---- reduce over the 8-lane group ----
        partial += __shfl_xor_sync(0xffffffffu, partial, 4);
        partial += __shfl_xor_sync(0xffffffffu, partial, 2);
        partial += __shfl_xor_sync(0xffffffffu, partial, 1);

        // ---- gather the 4 gates (group leaders at lanes 0,8,16,24) ----
        float pf = __shfl_sync(0xffffffffu, partial, 0);
        float pi = __shfl_sync(0xffffffffu, partial, 8);
        float pt = __shfl_sync(0xffffffffu, partial, 16);
        float po = __shfl_sync(0xffffffffu, partial, 24);

        // ---- activation (computed redundantly by all lanes; lane 0 stores) ----
        float f   = fast_sigmoid(pf);
        float ig  = fast_sigmoid(pi);
        float itv = fast_tanh(pt);
        float og  = fast_sigmoid(po);
        c = c * f + ig * itv;
        float h = fast_tanh(c) * og;

        if (l == 0) {
            g_hs[(size_t)t * 512 + j] = h;
            asm volatile("st.relaxed.gpu.global.v2.u32 [%0], {%1,%2};"
                         :: "l"(ht + j), "r"(__float_as_uint(h)), "r"((unsigned)(t + 1))
                         : "memory");
        }
    }
}

// ---------------- launch ----------------
template <typename Tsym>
static void* symaddr(Tsym& s)
{
    void* p = nullptr;
    cudaGetSymbolAddress(&p, s);
    return p;
}

extern "C" void kernel_launch(void* const* d_in, const int* in_sizes, int n_in,
                              void* d_out, int out_size)
{
    const int*   X      = (const int*)  d_in[0];
    const float* emb    = (const float*)d_in[1];
    const float* W_in   = (const float*)d_in[2];
    const float* b_in   = (const float*)d_in[3];
    const float* W_f    = (const float*)d_in[4];
    const float* b_f    = (const float*)d_in[5];
    const float* W_is   = (const float*)d_in[6];
    const float* b_is   = (const float*)d_in[7];
    const float* W_it   = (const float*)d_in[8];
    const float* b_it   = (const float*)d_in[9];
    const float* W_o    = (const float*)d_in[10];
    const float* b_o    = (const float*)d_in[11];
    const float* W_head = (const float*)d_in[12];
    const float* b_head = (const float*)d_in[13];
    float* out = (float*)d_out;

    float* xe   = (float*)symaddr(g_xe);
    float* xseq = (float*)symaddr(g_xseq);
    float* gx   = (float*)symaddr(g_gx);
    float* hs   = (float*)symaddr(g_hs);
    float* wxp  = (float*)symaddr(g_wxp);
    float* bx   = (float*)symaddr(g_bx);

    // 1. init scratch + repack weights (also resets h tags)
    init_repack<<<512, 256>>>(W_f, W_is, W_it, W_o, b_f, b_is, b_it, b_o);

    // 2. embedding gather
    gather_emb<<<(T_STEPS * EMBD + 255) / 256, 256>>>(X, emb);

    // 3. x projection: xseq = xe @ W_in + b_in   [4096,192]x[192,512]
    sgemm_bias<<<dim3(T_STEPS / 128, HIDDEN / 128), 256>>>(xe, W_in, b_in, xseq,
                                                           T_STEPS, HIDDEN, EMBD);

    // 4. gate x-part: gx = xseq @ Wxp + bx   [4096,512]x[512,2048]
    sgemm_bias<<<dim3(T_STEPS / 128, (4 * HIDDEN) / 128), 256>>>(xseq, wxp, bx, gx,
                                                                 T_STEPS, 4 * HIDDEN, HIDDEN);

    // 5. recurrence (persistent, 32 CTAs, tag-carried h exchange)
    lstm_rec<<<32, 512>>>();

    // 6. head: out = hs @ W_head + b_head   [4096,512]x[512,32000]
    sgemm_bias<<<dim3(T_STEPS / 128, VOCAB / 128), 256>>>(hs, W_head, b_head, out,
                                                          T_STEPS, VOCAB, HIDDEN);
}